// round 1
// baseline (speedup 1.0000x reference)
#include <cuda_runtime.h>
#include <cuda_bf16.h>

#define NND 50000
#define NE  800000
#define EDIM 64
#define NS  23
#define MDIM 87
#define HH  200
#define RDIM 256
#define NMOLS 2048

// ---------------- scratch (device globals; no allocations) ----------------
__device__ float g_x[NND * EDIM];      // current node features
__device__ float g_xall[NND * RDIM];   // concat of all passes
__device__ float g_m[NND * MDIM];      // aggregated messages
__device__ float g_h1[NND * HH];
__device__ float g_h2[NND * HH];
__device__ float g_stats[2 * RDIM];    // column sums / sumsq
__device__ float g_ac[2 * RDIM];       // folded BN affine: a, c

// ---------------- utility ----------------
__global__ void zero_kernel(float* __restrict__ p, int n) {
    int i = blockIdx.x * blockDim.x + threadIdx.x;
    if (i < n) p[i] = 0.f;
}

__global__ void embed_kernel(const int* __restrict__ z, const float* __restrict__ emb) {
    int i = blockIdx.x * blockDim.x + threadIdx.x;
    if (i >= NND * EDIM) return;
    int n = i >> 6, d = i & 63;
    float v = emb[(z[n] << 6) + d];
    g_x[i] = v;
    g_xall[(n << 8) + d] = v;   // RDIM == 256
}

// ---------------- edge scatter: m[src] += concat(rbf(d), x[sink]) ----------------
__global__ void scatter_kernel(const int* __restrict__ esrc,
                               const int* __restrict__ esnk,
                               const float* __restrict__ dist) {
    int gt = blockIdx.x * blockDim.x + threadIdx.x;
    int e = gt >> 5, lane = gt & 31;
    if (e >= NE) return;
    int src = esrc[e], snk = esnk[e];
    float d = dist[e];
    #pragma unroll
    for (int it = 0; it < 3; it++) {
        int f = lane + it * 32;
        if (f < MDIM) {
            float v;
            if (f < NS) {
                float t = d - (float)(0.8 + 0.1 * (double)f);
                v = __expf(-t * t);
            } else {
                v = g_x[snk * EDIM + (f - NS)];
            }
            atomicAdd(&g_m[src * MDIM + f], v);
        }
    }
}

// ---------------- batchnorm statistics ----------------
template <int C>
__global__ void stats_kernel(const float* __restrict__ X) {
    __shared__ float ssum[C], ssq[C];
    for (int i = threadIdx.x; i < C; i += blockDim.x) { ssum[i] = 0.f; ssq[i] = 0.f; }
    __syncthreads();
    int total = NND * C;
    for (int idx = blockIdx.x * blockDim.x + threadIdx.x; idx < total;
         idx += gridDim.x * blockDim.x) {
        float v = X[idx];
        int c = idx % C;
        atomicAdd(&ssum[c], v);
        atomicAdd(&ssq[c], v * v);
    }
    __syncthreads();
    for (int i = threadIdx.x; i < C; i += blockDim.x) {
        atomicAdd(&g_stats[i], ssum[i]);
        atomicAdd(&g_stats[C + i], ssq[i]);
    }
}

template <int C>
__global__ void bn_finalize(const float* __restrict__ g, const float* __restrict__ b) {
    int c = threadIdx.x;
    if (c >= C) return;
    const float inv = 1.f / (float)NND;
    float mean = g_stats[c] * inv;
    float var = fmaxf(g_stats[C + c] * inv - mean * mean, 0.f);
    float a = g[c] * rsqrtf(var + 1e-5f);
    g_ac[c] = a;
    g_ac[C + c] = b[c] - mean * a;
}

// ---------------- tiled fp32 GEMM: out = epi(A' @ W + bias) ----------------
// A' = A*a+c per column if BNIN. RELU optional. RESID: x += 0.1*out, also
// writes the g_xall slice at xall_off (NN must be EDIM=64 in that mode).
template <int K, int NN, bool RELU, bool BNIN, bool RESID>
__global__ __launch_bounds__(256)
void gemm_kernel(const float* __restrict__ A, const float* __restrict__ W,
                 const float* __restrict__ bias, float* __restrict__ out,
                 int xall_off) {
    const int BM = 64, BN = 64, BK = 16;
    __shared__ float As[BK][BM + 4];
    __shared__ float Bs[BK][BN];
    int bm = blockIdx.x * BM;
    int bn = blockIdx.y * BN;
    int tid = threadIdx.x;
    int tx = tid & 15, ty = tid >> 4;
    float acc[4][4] = {};

    for (int k0 = 0; k0 < K; k0 += BK) {
        #pragma unroll
        for (int i = 0; i < 4; i++) {
            int idx = tid + i * 256;
            int k = idx & 15, r = idx >> 4;
            int gr = bm + r, gk = k0 + k;
            float v = 0.f;
            if (gr < NND && gk < K) {
                v = A[gr * K + gk];
                if (BNIN) v = v * g_ac[gk] + g_ac[K + gk];
            }
            As[k][r] = v;
        }
        #pragma unroll
        for (int i = 0; i < 4; i++) {
            int idx = tid + i * 256;
            int n = idx & 63, k = idx >> 6;
            int gk = k0 + k, gn = bn + n;
            Bs[k][n] = (gk < K && gn < NN) ? W[gk * NN + gn] : 0.f;
        }
        __syncthreads();
        #pragma unroll
        for (int k = 0; k < BK; k++) {
            float4 a4 = *(const float4*)&As[k][ty * 4];
            float4 b4 = *(const float4*)&Bs[k][tx * 4];
            float a[4] = {a4.x, a4.y, a4.z, a4.w};
            float b[4] = {b4.x, b4.y, b4.z, b4.w};
            #pragma unroll
            for (int i = 0; i < 4; i++)
                #pragma unroll
                for (int j = 0; j < 4; j++) acc[i][j] += a[i] * b[j];
        }
        __syncthreads();
    }

    #pragma unroll
    for (int i = 0; i < 4; i++) {
        int gr = bm + ty * 4 + i;
        if (gr < NND) {
            #pragma unroll
            for (int j = 0; j < 4; j++) {
                int gn = bn + tx * 4 + j;
                if (gn < NN) {
                    float v = acc[i][j] + bias[gn];
                    if (RELU) v = fmaxf(v, 0.f);
                    if (RESID) {
                        float xn = g_x[gr * EDIM + gn] + 0.1f * v;
                        g_x[gr * EDIM + gn] = xn;
                        g_xall[gr * RDIM + xall_off + gn] = xn;
                    } else {
                        out[gr * NN + gn] = v;
                    }
                }
            }
        }
    }
}

// ---------------- final layer (H->1) + molecule scatter ----------------
__global__ void readout_final(const float* __restrict__ h, const float* __restrict__ w,
                              const float* __restrict__ b4, const int* __restrict__ mol,
                              float* __restrict__ y) {
    int gt = blockIdx.x * blockDim.x + threadIdx.x;
    int node = gt >> 5, lane = gt & 31;
    if (node >= NND) return;
    float s = 0.f;
    for (int k = lane; k < HH; k += 32) s += h[node * HH + k] * w[k];
    #pragma unroll
    for (int o = 16; o; o >>= 1) s += __shfl_xor_sync(0xffffffffu, s, o);
    if (lane == 0) atomicAdd(&y[mol[node]], s + b4[0]);
}

// ---------------- launch ----------------
extern "C" void kernel_launch(void* const* d_in, const int* in_sizes, int n_in,
                              void* d_out, int out_size) {
    const int*   z     = (const int*)d_in[0];
    const int*   eidx  = (const int*)d_in[1];
    const float* dist  = (const float*)d_in[2];
    const int*   mol   = (const int*)d_in[3];
    const float* emb   = (const float*)d_in[4];
    const float* up_bn_g = (const float*)d_in[5];
    const float* up_bn_b = (const float*)d_in[6];
    const float* up_w1 = (const float*)d_in[7];
    const float* up_b1 = (const float*)d_in[8];
    const float* up_w2 = (const float*)d_in[9];
    const float* up_b2 = (const float*)d_in[10];
    const float* up_w3 = (const float*)d_in[11];
    const float* up_b3 = (const float*)d_in[12];
    const float* up_w4 = (const float*)d_in[13];
    const float* up_b4 = (const float*)d_in[14];
    const float* ro_bn_g = (const float*)d_in[15];
    const float* ro_bn_b = (const float*)d_in[16];
    const float* ro_w1 = (const float*)d_in[17];
    const float* ro_b1 = (const float*)d_in[18];
    const float* ro_w2 = (const float*)d_in[19];
    const float* ro_b2 = (const float*)d_in[20];
    const float* ro_w3 = (const float*)d_in[21];
    const float* ro_b3 = (const float*)d_in[22];
    const float* ro_w4 = (const float*)d_in[23];
    const float* ro_b4 = (const float*)d_in[24];
    float* y = (float*)d_out;

    float *pm, *ph1, *ph2, *pxall, *pstats;
    cudaGetSymbolAddress((void**)&pm, g_m);
    cudaGetSymbolAddress((void**)&ph1, g_h1);
    cudaGetSymbolAddress((void**)&ph2, g_h2);
    cudaGetSymbolAddress((void**)&pxall, g_xall);
    cudaGetSymbolAddress((void**)&pstats, g_stats);

    zero_kernel<<<(NMOLS + 255) / 256, 256>>>(y, NMOLS);
    embed_kernel<<<(NND * EDIM + 255) / 256, 256>>>(z, emb);

    dim3 gH((NND + 63) / 64, (HH + 63) / 64);
    dim3 gE((NND + 63) / 64, 1);

    for (int t = 0; t < 3; t++) {
        zero_kernel<<<(NND * MDIM + 255) / 256, 256>>>(pm, NND * MDIM);
        scatter_kernel<<<NE / 8, 256>>>(eidx, eidx + NE, dist);
        zero_kernel<<<1, 256>>>(pstats, 2 * MDIM);
        stats_kernel<MDIM><<<512, 256>>>(pm);
        bn_finalize<MDIM><<<1, 256>>>(up_bn_g + t * MDIM, up_bn_b + t * MDIM);
        gemm_kernel<MDIM, HH, true, true, false><<<gH, 256>>>(
            pm, up_w1 + t * MDIM * HH, up_b1 + t * HH, ph1, 0);
        gemm_kernel<HH, HH, true, false, false><<<gH, 256>>>(
            ph1, up_w2 + t * HH * HH, up_b2 + t * HH, ph2, 0);
        gemm_kernel<HH, HH, true, false, false><<<gH, 256>>>(
            ph2, up_w3 + t * HH * HH, up_b3 + t * HH, ph1, 0);
        gemm_kernel<HH, EDIM, false, false, true><<<gE, 256>>>(
            ph1, up_w4 + t * HH * EDIM, up_b4 + t * EDIM, nullptr, EDIM * (t + 1));
    }

    zero_kernel<<<2, 256>>>(pstats, 2 * RDIM);
    stats_kernel<RDIM><<<512, 256>>>(pxall);
    bn_finalize<RDIM><<<1, 256>>>(ro_bn_g, ro_bn_b);
    gemm_kernel<RDIM, HH, true, true, false><<<gH, 256>>>(pxall, ro_w1, ro_b1, ph1, 0);
    gemm_kernel<HH, HH, true, false, false><<<gH, 256>>>(ph1, ro_w2, ro_b2, ph2, 0);
    gemm_kernel<HH, HH, true, false, false><<<gH, 256>>>(ph2, ro_w3, ro_b3, ph1, 0);
    readout_final<<<(NND * 32 + 255) / 256, 256>>>(ph1, ro_w4, ro_b4, mol, y);
}

// round 2
// speedup vs baseline: 1.0957x; 1.0957x over previous
#include <cuda_runtime.h>
#include <cuda_bf16.h>
#include <cstdint>

#define NND 50000
#define NE  800000
#define EDIM 64
#define NS  23
#define MDIM 87
#define HH  200
#define RDIM 256
#define NMOLS 2048

// ---------------- scratch (device globals; no allocations) ----------------
__device__ float g_x[NND * EDIM];      // current node features
__device__ float g_xall[NND * RDIM];   // concat of all passes
__device__ float g_mrbf[NND * NS];     // rbf part of aggregated messages (pass-invariant)
__device__ float g_mx[NND * EDIM];     // x part of aggregated messages (per pass)
__device__ float g_h1[NND * HH];
__device__ float g_h2[NND * HH];
__device__ float g_stats[2 * RDIM];    // column sums / sumsq
__device__ float g_ac[2 * RDIM];       // folded BN affine: a, c

// ---------------- utility ----------------
__global__ void zero_kernel(float* __restrict__ p, int n) {
    int i = blockIdx.x * blockDim.x + threadIdx.x;
    if (i < n) p[i] = 0.f;
}

__global__ void embed_kernel(const int* __restrict__ z, const float* __restrict__ emb) {
    int i = blockIdx.x * blockDim.x + threadIdx.x;
    if (i >= NND * EDIM) return;
    int n = i >> 6, d = i & 63;
    float v = emb[(z[n] << 6) + d];
    g_x[i] = v;
    g_xall[(n << 8) + d] = v;   // RDIM == 256
}

// ---------------- one-time rbf scatter (pass-invariant) ----------------
__global__ void scatter_rbf(const int* __restrict__ esrc, const float* __restrict__ dist) {
    int gt = blockIdx.x * blockDim.x + threadIdx.x;
    int e = gt >> 5, f = gt & 31;
    if (e >= NE || f >= NS) return;
    float d = dist[e];
    float t = d - (0.8f + 0.1f * (float)f);
    atomicAdd(&g_mrbf[esrc[e] * NS + f], __expf(-t * t));
}

// ---------------- per-pass x scatter: mx[src] += x[sink], vector atomics -----
__global__ void scatter_x(const int* __restrict__ esrc, const int* __restrict__ esnk) {
    int gt = blockIdx.x * blockDim.x + threadIdx.x;
    int e = gt >> 3, q = gt & 7;        // 8 lanes per edge, 2 float4 each
    if (e >= NE) return;
    int src = esrc[e], snk = esnk[e];
    const float4* xs = (const float4*)&g_x[snk * EDIM];
    float4* md = (float4*)&g_mx[src * EDIM];
    #pragma unroll
    for (int j = 0; j < 2; j++) {
        int qq = q + j * 8;
        float4 v = xs[qq];
        asm volatile("red.global.add.v4.f32 [%0], {%1,%2,%3,%4};"
                     :: "l"(md + qq), "f"(v.x), "f"(v.y), "f"(v.z), "f"(v.w)
                     : "memory");
    }
}

// ---------------- batchnorm statistics ----------------
template <int C, int OFF, int CTOT>
__global__ void stats_kernel(const float* __restrict__ X) {
    __shared__ float ssum[C], ssq[C];
    for (int i = threadIdx.x; i < C; i += blockDim.x) { ssum[i] = 0.f; ssq[i] = 0.f; }
    __syncthreads();
    int total = NND * C;
    for (int idx = blockIdx.x * blockDim.x + threadIdx.x; idx < total;
         idx += gridDim.x * blockDim.x) {
        float v = X[idx];
        int c = idx % C;
        atomicAdd(&ssum[c], v);
        atomicAdd(&ssq[c], v * v);
    }
    __syncthreads();
    for (int i = threadIdx.x; i < C; i += blockDim.x) {
        atomicAdd(&g_stats[OFF + i], ssum[i]);
        atomicAdd(&g_stats[CTOT + OFF + i], ssq[i]);
    }
}

template <int C>
__global__ void bn_finalize(const float* __restrict__ g, const float* __restrict__ b) {
    int c = threadIdx.x;
    if (c >= C) return;
    const float inv = 1.f / (float)NND;
    float mean = g_stats[c] * inv;
    float var = fmaxf(g_stats[C + c] * inv - mean * mean, 0.f);
    float a = g[c] * rsqrtf(var + 1e-5f);
    g_ac[c] = a;
    g_ac[C + c] = b[c] - mean * a;
}

// ---------------- tf32 tensor-core GEMM ----------------
__device__ __forceinline__ uint32_t f2tf32(float v) {
    uint32_t u;
    asm("cvt.rna.tf32.f32 %0, %1;" : "=r"(u) : "f"(v));
    return u;
}

__device__ __forceinline__ void mma_tf32(float* d, const uint32_t* a, const uint32_t* b) {
    asm volatile(
        "mma.sync.aligned.m16n8k8.row.col.f32.tf32.tf32.f32 "
        "{%0,%1,%2,%3}, {%4,%5,%6,%7}, {%8,%9}, {%0,%1,%2,%3};"
        : "+f"(d[0]), "+f"(d[1]), "+f"(d[2]), "+f"(d[3])
        : "r"(a[0]), "r"(a[1]), "r"(a[2]), "r"(a[3]), "r"(b[0]), "r"(b[1]));
}

// out = epi(A' @ W + bias); A' = A*a+c per column if BNIN.
// SPLITA: A comes from g_mrbf (first 23 cols) + g_mx (next 64), K==87.
// RESID: x += 0.1*out, also writes g_xall slice (NN must be 64).
template <int K, int NN, bool RELU, bool BNIN, bool RESID, bool SPLITA>
__global__ __launch_bounds__(256)
void gemm_tc(const float* __restrict__ A, const float* __restrict__ W,
             const float* __restrict__ bias, float* __restrict__ out,
             int xall_off) {
    const int BM = 128, BN = 64, BK = 32;
    __shared__ __align__(16) uint32_t As[BK][BM + 4];   // stride 132 ≡ 4 (mod 32)
    __shared__ __align__(16) uint32_t Bs[BK][BN + 4];   // stride 68  ≡ 4 (mod 32)
    int bm = blockIdx.x * BM;
    int bn = blockIdx.y * BN;
    int tid = threadIdx.x;
    int lane = tid & 31, wid = tid >> 5;
    int warp_m = wid & 3, warp_n = wid >> 2;            // 4x2 warp grid, 32x32 tiles
    int g = lane >> 2, tig = lane & 3;

    float acc[2][4][4];
    #pragma unroll
    for (int i = 0; i < 2; i++)
        #pragma unroll
        for (int j = 0; j < 4; j++)
            #pragma unroll
            for (int k = 0; k < 4; k++) acc[i][j][k] = 0.f;

    for (int k0 = 0; k0 < K; k0 += BK) {
        // ---- load A tile (BM x BK) ----
        if (SPLITA) {
            #pragma unroll
            for (int j = 0; j < 16; j++) {
                int idx = tid + j * 256;
                int row = idx >> 5, kk = idx & 31;
                int gr = bm + row, gk = k0 + kk;
                float v = 0.f;
                if (gr < NND && gk < K) {
                    v = (gk < NS) ? g_mrbf[gr * NS + gk] : g_mx[gr * EDIM + gk - NS];
                    if (BNIN) v = fmaf(v, g_ac[gk], g_ac[K + gk]);
                }
                As[kk][row] = f2tf32(v);
            }
        } else {
            #pragma unroll
            for (int j = 0; j < 4; j++) {
                int idx = tid + j * 256;          // float4 index over BM*BK/4
                int row = idx >> 3, kq = idx & 7;
                int gr = bm + row, gk = k0 + kq * 4;
                float4 v = {0.f, 0.f, 0.f, 0.f};
                if (gr < NND && gk < K) v = *(const float4*)&A[gr * K + gk];
                float vv[4] = {v.x, v.y, v.z, v.w};
                #pragma unroll
                for (int c = 0; c < 4; c++) {
                    float f = vv[c];
                    if (BNIN) f = fmaf(f, g_ac[gk + c], g_ac[K + gk + c]);
                    As[kq * 4 + c][row] = f2tf32(f);
                }
            }
        }
        // ---- load B tile (BK x BN) ----
        #pragma unroll
        for (int j = 0; j < 2; j++) {
            int idx = tid + j * 256;              // float4 index over BK*BN/4
            int krow = idx >> 4, nq = idx & 15;
            int gk = k0 + krow, gn = bn + nq * 4;
            float4 v = {0.f, 0.f, 0.f, 0.f};
            if (gk < K && gn < NN) v = *(const float4*)&W[gk * NN + gn];
            uint4 u;
            u.x = f2tf32(v.x); u.y = f2tf32(v.y); u.z = f2tf32(v.z); u.w = f2tf32(v.w);
            *(uint4*)&Bs[krow][nq * 4] = u;
        }
        __syncthreads();

        #pragma unroll
        for (int ks = 0; ks < 4; ks++) {
            int kb = ks * 8;
            uint32_t af[2][4], bf[4][2];
            #pragma unroll
            for (int mt = 0; mt < 2; mt++) {
                int r = warp_m * 32 + mt * 16 + g;
                af[mt][0] = As[kb + tig][r];
                af[mt][1] = As[kb + tig][r + 8];
                af[mt][2] = As[kb + tig + 4][r];
                af[mt][3] = As[kb + tig + 4][r + 8];
            }
            #pragma unroll
            for (int nt = 0; nt < 4; nt++) {
                int c = warp_n * 32 + nt * 8 + g;
                bf[nt][0] = Bs[kb + tig][c];
                bf[nt][1] = Bs[kb + tig + 4][c];
            }
            #pragma unroll
            for (int mt = 0; mt < 2; mt++)
                #pragma unroll
                for (int nt = 0; nt < 4; nt++)
                    mma_tf32(acc[mt][nt], af[mt], bf[nt]);
        }
        __syncthreads();
    }

    // ---- epilogue ----
    #pragma unroll
    for (int mt = 0; mt < 2; mt++) {
        #pragma unroll
        for (int nt = 0; nt < 4; nt++) {
            int r0 = bm + warp_m * 32 + mt * 16 + g;
            int c0 = bn + warp_n * 32 + nt * 8 + tig * 2;
            float* d = acc[mt][nt];
            #pragma unroll
            for (int h = 0; h < 2; h++) {        // h=0 -> row r0, h=1 -> row r0+8
                int r = r0 + h * 8;
                if (r < NND && c0 < NN) {
                    float v0 = d[h * 2 + 0] + bias[c0];
                    float v1 = d[h * 2 + 1] + bias[c0 + 1];
                    if (RELU) { v0 = fmaxf(v0, 0.f); v1 = fmaxf(v1, 0.f); }
                    if (RESID) {
                        float2 xo = *(float2*)&g_x[r * EDIM + c0];
                        float2 xn = {xo.x + 0.1f * v0, xo.y + 0.1f * v1};
                        *(float2*)&g_x[r * EDIM + c0] = xn;
                        *(float2*)&g_xall[r * RDIM + xall_off + c0] = xn;
                    } else {
                        *(float2*)&out[r * NN + c0] = {v0, v1};
                    }
                }
            }
        }
    }
}

// ---------------- final layer (H->1) + molecule scatter ----------------
__global__ void readout_final(const float* __restrict__ h, const float* __restrict__ w,
                              const float* __restrict__ b4, const int* __restrict__ mol,
                              float* __restrict__ y) {
    int gt = blockIdx.x * blockDim.x + threadIdx.x;
    int node = gt >> 5, lane = gt & 31;
    if (node >= NND) return;
    float s = 0.f;
    for (int k = lane; k < HH; k += 32) s += h[node * HH + k] * w[k];
    #pragma unroll
    for (int o = 16; o; o >>= 1) s += __shfl_xor_sync(0xffffffffu, s, o);
    if (lane == 0) atomicAdd(&y[mol[node]], s + b4[0]);
}

// ---------------- launch ----------------
extern "C" void kernel_launch(void* const* d_in, const int* in_sizes, int n_in,
                              void* d_out, int out_size) {
    const int*   z     = (const int*)d_in[0];
    const int*   eidx  = (const int*)d_in[1];
    const float* dist  = (const float*)d_in[2];
    const int*   mol   = (const int*)d_in[3];
    const float* emb   = (const float*)d_in[4];
    const float* up_bn_g = (const float*)d_in[5];
    const float* up_bn_b = (const float*)d_in[6];
    const float* up_w1 = (const float*)d_in[7];
    const float* up_b1 = (const float*)d_in[8];
    const float* up_w2 = (const float*)d_in[9];
    const float* up_b2 = (const float*)d_in[10];
    const float* up_w3 = (const float*)d_in[11];
    const float* up_b3 = (const float*)d_in[12];
    const float* up_w4 = (const float*)d_in[13];
    const float* up_b4 = (const float*)d_in[14];
    const float* ro_bn_g = (const float*)d_in[15];
    const float* ro_bn_b = (const float*)d_in[16];
    const float* ro_w1 = (const float*)d_in[17];
    const float* ro_b1 = (const float*)d_in[18];
    const float* ro_w2 = (const float*)d_in[19];
    const float* ro_b2 = (const float*)d_in[20];
    const float* ro_w3 = (const float*)d_in[21];
    const float* ro_b3 = (const float*)d_in[22];
    const float* ro_w4 = (const float*)d_in[23];
    const float* ro_b4 = (const float*)d_in[24];
    float* y = (float*)d_out;

    float *pmrbf, *pmx, *ph1, *ph2, *pxall, *pstats;
    cudaGetSymbolAddress((void**)&pmrbf, g_mrbf);
    cudaGetSymbolAddress((void**)&pmx, g_mx);
    cudaGetSymbolAddress((void**)&ph1, g_h1);
    cudaGetSymbolAddress((void**)&ph2, g_h2);
    cudaGetSymbolAddress((void**)&pxall, g_xall);
    cudaGetSymbolAddress((void**)&pstats, g_stats);

    zero_kernel<<<(NMOLS + 255) / 256, 256>>>(y, NMOLS);
    embed_kernel<<<(NND * EDIM + 255) / 256, 256>>>(z, emb);

    // one-time rbf scatter + its (pass-invariant) BN column stats
    zero_kernel<<<(NND * NS + 255) / 256, 256>>>(pmrbf, NND * NS);
    zero_kernel<<<2, 256>>>(pstats, 2 * RDIM);
    scatter_rbf<<<(NE * 32) / 256, 256>>>(eidx, dist);
    stats_kernel<NS, 0, MDIM><<<512, 256>>>(pmrbf);

    dim3 gH((NND + 127) / 128, (HH + 63) / 64);    // 391 x 4
    dim3 gE((NND + 127) / 128, 1);                 // 391 x 1

    for (int t = 0; t < 3; t++) {
        zero_kernel<<<(NND * EDIM + 255) / 256, 256>>>(pmx, NND * EDIM);
        scatter_x<<<(NE * 8) / 256, 256>>>(eidx, eidx + NE);
        zero_kernel<<<1, 64>>>(pstats + NS, EDIM);
        zero_kernel<<<1, 64>>>(pstats + MDIM + NS, EDIM);
        stats_kernel<EDIM, NS, MDIM><<<512, 256>>>(pmx);
        bn_finalize<MDIM><<<1, 256>>>(up_bn_g + t * MDIM, up_bn_b + t * MDIM);
        gemm_tc<MDIM, HH, true, true, false, true><<<gH, 256>>>(
            nullptr, up_w1 + t * MDIM * HH, up_b1 + t * HH, ph1, 0);
        gemm_tc<HH, HH, true, false, false, false><<<gH, 256>>>(
            ph1, up_w2 + t * HH * HH, up_b2 + t * HH, ph2, 0);
        gemm_tc<HH, HH, true, false, false, false><<<gH, 256>>>(
            ph2, up_w3 + t * HH * HH, up_b3 + t * HH, ph1, 0);
        gemm_tc<HH, EDIM, false, false, true, false><<<gE, 256>>>(
            ph1, up_w4 + t * HH * EDIM, up_b4 + t * EDIM, nullptr, EDIM * (t + 1));
    }

    zero_kernel<<<2, 256>>>(pstats, 2 * RDIM);
    stats_kernel<RDIM, 0, RDIM><<<512, 256>>>(pxall);
    bn_finalize<RDIM><<<1, 256>>>(ro_bn_g, ro_bn_b);
    gemm_tc<RDIM, HH, true, true, false, false><<<gH, 256>>>(pxall, ro_w1, ro_b1, ph1, 0);
    gemm_tc<HH, HH, true, false, false, false><<<gH, 256>>>(ph1, ro_w2, ro_b2, ph2, 0);
    gemm_tc<HH, HH, true, false, false, false><<<gH, 256>>>(ph2, ro_w3, ro_b3, ph1, 0);
    readout_final<<<(NND * 32 + 255) / 256, 256>>>(ph1, ro_w4, ro_b4, mol, y);
}

// round 4
// speedup vs baseline: 2.3229x; 2.1200x over previous
#include <cuda_runtime.h>
#include <cuda_bf16.h>
#include <cstdint>

#define NND 50000
#define NE  800000
#define EDIM 64
#define NS  23
#define MDIM 87
#define HH  200
#define RDIM 256
#define NMOLS 2048

// ---------------- scratch (device globals; no allocations) ----------------
__device__ float g_x[NND * EDIM];
__device__ float g_xall[NND * RDIM];
__device__ float g_mrbf[NND * 24];      // padded to 24 cols for red.v4
__device__ float g_mx[NND * EDIM];
__device__ float g_h1[NND * HH];        // pre-rounded tf32 bits
__device__ float g_h2[NND * HH];        // pre-rounded tf32 bits
__device__ float g_stats[2 * RDIM];
__device__ float g_ac[2 * RDIM];
__device__ float g_wT[470000];          // tf32-pre-rounded weights (original layout)

// wT offsets (floats)
#define WT_UP1 0        // 3 x 87x200  = 52200
#define WT_UP2 52200    // 3 x 200x200 = 120000
#define WT_UP3 172200   // 3 x 200x200 = 120000
#define WT_UP4 292200   // 3 x 200x64  = 38400
#define WT_RO1 330600   // 256x200     = 51200
#define WT_RO2 381800   // 200x200     = 40000
#define WT_RO3 421800   // 200x200     = 40000

// ---------------- helpers ----------------
__device__ __forceinline__ uint32_t smem_u32(const void* p) {
    uint32_t a;
    asm("{ .reg .u64 t; cvta.to.shared.u64 t, %1; cvt.u32.u64 %0, t; }" : "=r"(a) : "l"(p));
    return a;
}
__device__ __forceinline__ uint32_t f2tf32(float v) {
    uint32_t u;
    asm("cvt.rna.tf32.f32 %0, %1;" : "=r"(u) : "f"(v));
    return u;
}
__device__ __forceinline__ void cp_async16(uint32_t dst, const void* src, int valid) {
    asm volatile("cp.async.cg.shared.global [%0], [%1], 16, %2;"
                 :: "r"(dst), "l"(src), "r"(valid) : "memory");
}
__device__ __forceinline__ void mma_tf32(float* d, const uint32_t* a, const uint32_t* b) {
    asm volatile(
        "mma.sync.aligned.m16n8k8.row.col.f32.tf32.tf32.f32 "
        "{%0,%1,%2,%3}, {%4,%5,%6,%7}, {%8,%9}, {%0,%1,%2,%3};"
        : "+f"(d[0]), "+f"(d[1]), "+f"(d[2]), "+f"(d[3])
        : "r"(a[0]), "r"(a[1]), "r"(a[2]), "r"(a[3]), "r"(b[0]), "r"(b[1]));
}

// ---------------- utility kernels ----------------
__global__ void zero_kernel(float* __restrict__ p, int n) {
    int i = blockIdx.x * blockDim.x + threadIdx.x;
    if (i < n) p[i] = 0.f;
}

__global__ void round_w(const float* __restrict__ in, float* __restrict__ out, int n) {
    int i = blockIdx.x * blockDim.x + threadIdx.x;
    if (i < n) out[i] = __uint_as_float(f2tf32(in[i]));
}

__global__ void embed_kernel(const int* __restrict__ z, const float* __restrict__ emb) {
    int i = blockIdx.x * blockDim.x + threadIdx.x;
    if (i >= NND * EDIM) return;
    int n = i >> 6, d = i & 63;
    float v = emb[(z[n] << 6) + d];
    g_x[i] = v;
    g_xall[(n << 8) + d] = v;
}

// ---------------- scatters ----------------
__global__ void scatter_rbf(const int* __restrict__ esrc, const float* __restrict__ dist) {
    int gt = blockIdx.x * blockDim.x + threadIdx.x;
    int e = gt >> 3, q = gt & 7;
    if (e >= NE || q >= 6) return;
    float d = dist[e];
    int src = esrc[e];
    float v[4];
    #pragma unroll
    for (int j = 0; j < 4; j++) {
        int f = q * 4 + j;
        float t = d - (0.8f + 0.1f * (float)f);
        v[j] = (f < NS) ? __expf(-t * t) : 0.f;
    }
    asm volatile("red.global.add.v4.f32 [%0], {%1,%2,%3,%4};"
                 :: "l"(g_mrbf + src * 24 + q * 4),
                    "f"(v[0]), "f"(v[1]), "f"(v[2]), "f"(v[3]) : "memory");
}

__global__ void scatter_x(const int* __restrict__ esrc, const int* __restrict__ esnk) {
    int gt = blockIdx.x * blockDim.x + threadIdx.x;
    int e = gt >> 3, q = gt & 7;
    if (e >= NE) return;
    int src = esrc[e], snk = esnk[e];
    const float4* xs = (const float4*)&g_x[snk * EDIM];
    float4* md = (float4*)&g_mx[src * EDIM];
    #pragma unroll
    for (int j = 0; j < 2; j++) {
        int qq = q + j * 8;
        float4 v = xs[qq];
        asm volatile("red.global.add.v4.f32 [%0], {%1,%2,%3,%4};"
                     :: "l"(md + qq), "f"(v.x), "f"(v.y), "f"(v.z), "f"(v.w) : "memory");
    }
}

// ---------------- batchnorm stats ----------------
// register-accumulating: column = tid & (C-1); requires C | 256
template <int C, int OFF, int CTOT>
__global__ void stats_reg(const float* __restrict__ X) {
    int tid = threadIdx.x;
    int col = tid & (C - 1);
    float s = 0.f, q = 0.f;
    int stride = gridDim.x * 256;
    for (int idx = blockIdx.x * 256 + tid; idx < NND * C; idx += stride) {
        float v = X[idx];
        s += v; q += v * v;
    }
    __shared__ float sh[512];
    sh[tid] = s; sh[256 + tid] = q;
    __syncthreads();
    if (tid < C) {
        float S = 0.f, Q = 0.f;
        #pragma unroll 4
        for (int j = tid; j < 256; j += C) { S += sh[j]; Q += sh[256 + j]; }
        atomicAdd(&g_stats[OFF + tid], S);
        atomicAdd(&g_stats[CTOT + OFF + tid], Q);
    }
}

// rbf stats (one-time, C=23 over stride-24 array)
__global__ void stats_rbf() {
    __shared__ float ss[24], sq[24];
    if (threadIdx.x < 24) { ss[threadIdx.x] = 0.f; sq[threadIdx.x] = 0.f; }
    __syncthreads();
    int stride = gridDim.x * blockDim.x;
    for (int idx = blockIdx.x * blockDim.x + threadIdx.x; idx < NND * 24; idx += stride) {
        int c = idx % 24;
        if (c < NS) {
            float v = g_mrbf[idx];
            atomicAdd(&ss[c], v);
            atomicAdd(&sq[c], v * v);
        }
    }
    __syncthreads();
    if (threadIdx.x < NS) {
        atomicAdd(&g_stats[threadIdx.x], ss[threadIdx.x]);
        atomicAdd(&g_stats[MDIM + threadIdx.x], sq[threadIdx.x]);
    }
}

template <int C>
__global__ void bn_finalize(const float* __restrict__ g, const float* __restrict__ b) {
    int c = threadIdx.x;
    if (c >= C) return;
    const float inv = 1.f / (float)NND;
    float mean = g_stats[c] * inv;
    float var = fmaxf(g_stats[C + c] * inv - mean * mean, 0.f);
    float a = g[c] * rsqrtf(var + 1e-5f);
    g_ac[c] = a;
    g_ac[C + c] = b[c] - mean * a;
}

// ---------------- double-buffered tf32 mma GEMM ----------------
// D[128 x NN tile] = epi(A' @ W + bias).  W: [K][NW] tf32-pre-rounded.
// SPLITA: A from g_mrbf(23, stride24) + g_mx(64), fold BN.  BNIN: fold BN at load.
// otherwise A is pre-rounded tf32 bits -> cp.async raw.
// RESID: g_x += 0.1*D + write g_xall slice (fp32).  ROUND_OUT: store tf32-rounded.
template <int KTOT, int NCH, int NN, int NW, bool RELU, bool BNIN, bool RESID,
          bool SPLITA, bool ROUND_OUT>
__global__ __launch_bounds__(256)
void gemm_mma(const float* __restrict__ A, const float* __restrict__ W,
              const float* __restrict__ bias, float* __restrict__ out, int xall_off) {
    constexpr int AW = 128 * 20;   // A stage words ([r][k], stride 20)
    constexpr int BW = 16 * 68;    // B stage words ([k][n], stride 68)
    __shared__ __align__(16) uint32_t sbuf[2][AW + BW];

    int tid = threadIdx.x, lane = tid & 31, wid = tid >> 5;
    int warp_m = wid & 3, warp_n = wid >> 2;
    int g = lane >> 2, tig = lane & 3;
    int bm = blockIdx.x * 128, bn = blockIdx.y * 64;
    uint32_t sbase = smem_u32(sbuf);

    float acc[2][4][4] = {};

#define STAGE(cc, bb) do { \
    int k0_ = (cc) * 16; \
    uint32_t* As_ = sbuf[bb]; \
    uint32_t aAdr_ = sbase + (uint32_t)(bb) * (AW + BW) * 4; \
    uint32_t bAdr_ = aAdr_ + AW * 4; \
    if (SPLITA) { \
        _Pragma("unroll") \
        for (int j = 0; j < 8; j++) { \
            int idx = tid + j * 256; \
            int row = idx >> 4, kk = idx & 15; \
            int gr = bm + row, gk = k0_ + kk; \
            float v = 0.f; \
            if (gr < NND && gk < KTOT) { \
                v = (gk < NS) ? g_mrbf[gr * 24 + gk] : g_mx[gr * 64 + gk - NS]; \
                v = fmaf(v, g_ac[gk], g_ac[KTOT + gk]); \
            } \
            As_[row * 20 + kk] = f2tf32(v); \
        } \
    } else if (BNIN) { \
        _Pragma("unroll") \
        for (int j = 0; j < 2; j++) { \
            int idx = tid + j * 256; \
            int row = idx >> 2, kq = idx & 3; \
            int gr = bm + row, gk = k0_ + kq * 4; \
            float4 v = {0.f, 0.f, 0.f, 0.f}; \
            if (gr < NND && gk < KTOT) v = *(const float4*)(A + (size_t)gr * KTOT + gk); \
            uint4 u; \
            u.x = f2tf32((gr < NND) ? fmaf(v.x, g_ac[gk + 0], g_ac[KTOT + gk + 0]) : 0.f); \
            u.y = f2tf32((gr < NND) ? fmaf(v.y, g_ac[gk + 1], g_ac[KTOT + gk + 1]) : 0.f); \
            u.z = f2tf32((gr < NND) ? fmaf(v.z, g_ac[gk + 2], g_ac[KTOT + gk + 2]) : 0.f); \
            u.w = f2tf32((gr < NND) ? fmaf(v.w, g_ac[gk + 3], g_ac[KTOT + gk + 3]) : 0.f); \
            *(uint4*)&As_[row * 20 + kq * 4] = u; \
        } \
    } else { \
        _Pragma("unroll") \
        for (int j = 0; j < 2; j++) { \
            int idx = tid + j * 256; \
            int row = idx >> 2, kq = idx & 3; \
            int gr = bm + row, gk = k0_ + kq * 4; \
            int vld = (gr < NND && gk + 4 <= KTOT) ? 16 : 0; \
            const float* src = vld ? (A + (size_t)gr * KTOT + gk) : A; \
            cp_async16(aAdr_ + (uint32_t)(row * 20 + kq * 4) * 4, src, vld); \
        } \
    } \
    { \
        int kk = tid >> 4, nq = tid & 15; \
        int gk = k0_ + kk, gn = bn + nq * 4; \
        int vld = (gk < KTOT && gn + 4 <= NW) ? 16 : 0; \
        const float* src = vld ? (W + (size_t)gk * NW + gn) : W; \
        cp_async16(bAdr_ + (uint32_t)(kk * 68 + nq * 4) * 4, src, vld); \
    } \
    asm volatile("cp.async.commit_group;" ::: "memory"); \
} while (0)

    STAGE(0, 0);
    for (int c = 0; c < NCH; c++) {
        if (c + 1 < NCH) {
            STAGE(c + 1, (c + 1) & 1);
            asm volatile("cp.async.wait_group 1;" ::: "memory");
        } else {
            asm volatile("cp.async.wait_group 0;" ::: "memory");
        }
        __syncthreads();
        const uint32_t* As = sbuf[c & 1];
        const uint32_t* Bs = sbuf[c & 1] + AW;
        #pragma unroll
        for (int ks = 0; ks < 2; ks++) {
            int kb = ks * 8;
            uint32_t af[2][4], bf[4][2];
            #pragma unroll
            for (int mt = 0; mt < 2; mt++) {
                int r0 = (warp_m * 32 + mt * 16 + g) * 20;
                af[mt][0] = As[r0 + kb + tig];
                af[mt][1] = As[r0 + 160 + kb + tig];
                af[mt][2] = As[r0 + kb + tig + 4];
                af[mt][3] = As[r0 + 160 + kb + tig + 4];
            }
            #pragma unroll
            for (int nt = 0; nt < 4; nt++) {
                int cc = warp_n * 32 + nt * 8 + g;
                bf[nt][0] = Bs[(kb + tig) * 68 + cc];
                bf[nt][1] = Bs[(kb + tig + 4) * 68 + cc];
            }
            #pragma unroll
            for (int mt = 0; mt < 2; mt++)
                #pragma unroll
                for (int nt = 0; nt < 4; nt++)
                    mma_tf32(acc[mt][nt], af[mt], bf[nt]);
        }
        __syncthreads();
    }
#undef STAGE

    // ---- epilogue ----
    #pragma unroll
    for (int mt = 0; mt < 2; mt++) {
        #pragma unroll
        for (int nt = 0; nt < 4; nt++) {
            int r0 = bm + warp_m * 32 + mt * 16 + g;
            int c0 = bn + warp_n * 32 + nt * 8 + tig * 2;
            float* d = acc[mt][nt];
            #pragma unroll
            for (int h = 0; h < 2; h++) {
                int r = r0 + h * 8;
                if (r < NND && c0 < NN) {
                    float v0 = d[h * 2 + 0] + __ldg(bias + c0);
                    float v1 = d[h * 2 + 1] + __ldg(bias + c0 + 1);
                    if (RELU) { v0 = fmaxf(v0, 0.f); v1 = fmaxf(v1, 0.f); }
                    if (RESID) {
                        float2 xo = *(float2*)&g_x[r * EDIM + c0];
                        float2 xn = {xo.x + 0.1f * v0, xo.y + 0.1f * v1};
                        *(float2*)&g_x[r * EDIM + c0] = xn;
                        *(float2*)&g_xall[r * RDIM + xall_off + c0] = xn;
                    } else {
                        if (ROUND_OUT) {
                            v0 = __uint_as_float(f2tf32(v0));
                            v1 = __uint_as_float(f2tf32(v1));
                        }
                        *(float2*)&out[(size_t)r * NN + c0] = {v0, v1};
                    }
                }
            }
        }
    }
}

// ---------------- final layer (H->1) + molecule scatter ----------------
__global__ void readout_final(const float* __restrict__ h, const float* __restrict__ w,
                              const float* __restrict__ b4, const int* __restrict__ mol,
                              float* __restrict__ y) {
    int gt = blockIdx.x * blockDim.x + threadIdx.x;
    int node = gt >> 5, lane = gt & 31;
    if (node >= NND) return;
    float s = 0.f;
    for (int k = lane; k < HH; k += 32) s += h[node * HH + k] * w[k];
    #pragma unroll
    for (int o = 16; o; o >>= 1) s += __shfl_xor_sync(0xffffffffu, s, o);
    if (lane == 0) atomicAdd(&y[mol[node]], s + b4[0]);
}

// ---------------- launch ----------------
extern "C" void kernel_launch(void* const* d_in, const int* in_sizes, int n_in,
                              void* d_out, int out_size) {
    const int*   z     = (const int*)d_in[0];
    const int*   eidx  = (const int*)d_in[1];
    const float* dist  = (const float*)d_in[2];
    const int*   mol   = (const int*)d_in[3];
    const float* emb   = (const float*)d_in[4];
    const float* up_bn_g = (const float*)d_in[5];
    const float* up_bn_b = (const float*)d_in[6];
    const float* up_w1 = (const float*)d_in[7];
    const float* up_b1 = (const float*)d_in[8];
    const float* up_w2 = (const float*)d_in[9];
    const float* up_b2 = (const float*)d_in[10];
    const float* up_w3 = (const float*)d_in[11];
    const float* up_b3 = (const float*)d_in[12];
    const float* up_w4 = (const float*)d_in[13];
    const float* up_b4 = (const float*)d_in[14];
    const float* ro_bn_g = (const float*)d_in[15];
    const float* ro_bn_b = (const float*)d_in[16];
    const float* ro_w1 = (const float*)d_in[17];
    const float* ro_b1 = (const float*)d_in[18];
    const float* ro_w2 = (const float*)d_in[19];
    const float* ro_b2 = (const float*)d_in[20];
    const float* ro_w3 = (const float*)d_in[21];
    const float* ro_b3 = (const float*)d_in[22];
    const float* ro_w4 = (const float*)d_in[23];
    const float* ro_b4 = (const float*)d_in[24];
    float* y = (float*)d_out;

    float *pmrbf, *pmx, *ph1, *ph2, *pxall, *pstats, *pwT;
    cudaGetSymbolAddress((void**)&pmrbf, g_mrbf);
    cudaGetSymbolAddress((void**)&pmx, g_mx);
    cudaGetSymbolAddress((void**)&ph1, g_h1);
    cudaGetSymbolAddress((void**)&ph2, g_h2);
    cudaGetSymbolAddress((void**)&pxall, g_xall);
    cudaGetSymbolAddress((void**)&pstats, g_stats);
    cudaGetSymbolAddress((void**)&pwT, g_wT);

    zero_kernel<<<(NMOLS + 255) / 256, 256>>>(y, NMOLS);
    embed_kernel<<<(NND * EDIM + 255) / 256, 256>>>(z, emb);

    // pre-round weights to tf32 (one-time, original layout)
    round_w<<<(52200 + 255) / 256, 256>>>(up_w1, pwT + WT_UP1, 52200);
    round_w<<<(120000 + 255) / 256, 256>>>(up_w2, pwT + WT_UP2, 120000);
    round_w<<<(120000 + 255) / 256, 256>>>(up_w3, pwT + WT_UP3, 120000);
    round_w<<<(38400 + 255) / 256, 256>>>(up_w4, pwT + WT_UP4, 38400);
    round_w<<<(51200 + 255) / 256, 256>>>(ro_w1, pwT + WT_RO1, 51200);
    round_w<<<(40000 + 255) / 256, 256>>>(ro_w2, pwT + WT_RO2, 40000);
    round_w<<<(40000 + 255) / 256, 256>>>(ro_w3, pwT + WT_RO3, 40000);

    // one-time rbf scatter + its pass-invariant stats
    zero_kernel<<<(NND * 24 + 255) / 256, 256>>>(pmrbf, NND * 24);
    zero_kernel<<<2, 256>>>(pstats, 2 * RDIM);
    scatter_rbf<<<(NE * 8 + 255) / 256, 256>>>(eidx, dist);
    stats_rbf<<<296, 256>>>();

    const int GB = (NND + 127) / 128;   // 391
    dim3 gH(GB, 4), gE(GB, 1);

    for (int t = 0; t < 3; t++) {
        zero_kernel<<<(NND * EDIM + 255) / 256, 256>>>(pmx, NND * EDIM);
        scatter_x<<<(NE * 8) / 256, 256>>>(eidx, eidx + NE);
        zero_kernel<<<1, 64>>>(pstats + NS, EDIM);
        zero_kernel<<<1, 64>>>(pstats + MDIM + NS, EDIM);
        stats_reg<EDIM, NS, MDIM><<<296, 256>>>(pmx);
        bn_finalize<MDIM><<<1, 256>>>(up_bn_g + t * MDIM, up_bn_b + t * MDIM);
        // K=87 -> 6 chunks; K=200 -> 13 chunks
        gemm_mma<MDIM, 6, HH, HH, true, true, false, true, true><<<gH, 256>>>(
            nullptr, pwT + WT_UP1 + t * MDIM * HH, up_b1 + t * HH, ph1, 0);
        gemm_mma<HH, 13, HH, HH, true, false, false, false, true><<<gH, 256>>>(
            ph1, pwT + WT_UP2 + t * HH * HH, up_b2 + t * HH, ph2, 0);
        gemm_mma<HH, 13, HH, HH, true, false, false, false, true><<<gH, 256>>>(
            ph2, pwT + WT_UP3 + t * HH * HH, up_b3 + t * HH, ph1, 0);
        gemm_mma<HH, 13, EDIM, EDIM, false, false, true, false, false><<<gE, 256>>>(
            ph1, pwT + WT_UP4 + t * HH * EDIM, up_b4 + t * EDIM, nullptr, EDIM * (t + 1));
    }

    zero_kernel<<<2, 256>>>(pstats, 2 * RDIM);
    stats_reg<RDIM, 0, RDIM><<<296, 256>>>(pxall);
    bn_finalize<RDIM><<<1, 256>>>(ro_bn_g, ro_bn_b);
    gemm_mma<RDIM, 16, HH, HH, true, true, false, false, true><<<gH, 256>>>(
        pxall, pwT + WT_RO1, ro_b1, ph1, 0);
    gemm_mma<HH, 13, HH, HH, true, false, false, false, true><<<gH, 256>>>(
        ph1, pwT + WT_RO2, ro_b2, ph2, 0);
    gemm_mma<HH, 13, HH, HH, true, false, false, false, true><<<gH, 256>>>(
        ph2, pwT + WT_RO3, ro_b3, ph1, 0);
    readout_final<<<(NND * 32 + 255) / 256, 256>>>(ph1, ro_w4, ro_b4, mol, y);
}

// round 8
// speedup vs baseline: 2.4669x; 1.0620x over previous
#include <cuda_runtime.h>
#include <cuda_bf16.h>
#include <cstdint>

#define NND 50000
#define NE  800000
#define EDIM 64
#define NS  23
#define MDIM 87
#define HH  200
#define RDIM 256
#define NMOLS 2048
#define NB_SCAN 196   // ceil(NND/256)

// ---------------- scratch (device globals; no allocations) ----------------
__device__ float g_x[NND * EDIM];
__device__ float g_xall[NND * RDIM];
__device__ float g_mrbf[NND * 24];
__device__ float g_mx[NND * EDIM];
__device__ float g_h1[NND * HH];        // pre-rounded tf32 bits
__device__ float g_h2[NND * HH];        // pre-rounded tf32 bits
__device__ float g_stats[2 * RDIM];
__device__ float g_ac[2 * RDIM];
__device__ float g_wT[470000];          // tf32-pre-rounded weights
// CSR scratch
__device__ int   g_cnt[NND];
__device__ int   g_excl[NND];
__device__ int   g_bsum[256];
__device__ int   g_boff[256];
__device__ int   g_row[NND + 1];
__device__ int   g_pos[NND];
__device__ int   g_esnk_s[NE];
__device__ float g_edist_s[NE];

// wT offsets (floats)
#define WT_UP1 0
#define WT_UP2 52200
#define WT_UP3 172200
#define WT_UP4 292200
#define WT_RO1 330600
#define WT_RO2 381800
#define WT_RO3 421800

// ---------------- helpers ----------------
__device__ __forceinline__ uint32_t smem_u32(const void* p) {
    uint32_t a;
    asm("{ .reg .u64 t; cvta.to.shared.u64 t, %1; cvt.u32.u64 %0, t; }" : "=r"(a) : "l"(p));
    return a;
}
__device__ __forceinline__ uint32_t f2tf32(float v) {
    uint32_t u;
    asm("cvt.rna.tf32.f32 %0, %1;" : "=r"(u) : "f"(v));
    return u;
}
__device__ __forceinline__ void cp_async16(uint32_t dst, const void* src, int valid) {
    asm volatile("cp.async.cg.shared.global [%0], [%1], 16, %2;"
                 :: "r"(dst), "l"(src), "r"(valid) : "memory");
}
__device__ __forceinline__ void mma_tf32(float* d, const uint32_t* a, const uint32_t* b) {
    asm volatile(
        "mma.sync.aligned.m16n8k8.row.col.f32.tf32.tf32.f32 "
        "{%0,%1,%2,%3}, {%4,%5,%6,%7}, {%8,%9}, {%0,%1,%2,%3};"
        : "+f"(d[0]), "+f"(d[1]), "+f"(d[2]), "+f"(d[3])
        : "r"(a[0]), "r"(a[1]), "r"(a[2]), "r"(a[3]), "r"(b[0]), "r"(b[1]));
}

// ---------------- utility kernels ----------------
__global__ void zero_kernel(float* __restrict__ p, int n) {
    int i = blockIdx.x * blockDim.x + threadIdx.x;
    if (i < n) p[i] = 0.f;
}
__global__ void zero_int(int* __restrict__ p, int n) {
    int i = blockIdx.x * blockDim.x + threadIdx.x;
    if (i < n) p[i] = 0;
}
__global__ void round_w(const float* __restrict__ in, float* __restrict__ out, int n) {
    int i = blockIdx.x * blockDim.x + threadIdx.x;
    if (i < n) out[i] = __uint_as_float(f2tf32(in[i]));
}
__global__ void embed_kernel(const int* __restrict__ z, const float* __restrict__ emb) {
    int i = blockIdx.x * blockDim.x + threadIdx.x;
    if (i >= NND * EDIM) return;
    int n = i >> 6, d = i & 63;
    float v = emb[(z[n] << 6) + d];
    g_x[i] = v;
    g_xall[(n << 8) + d] = v;
}

// ---------------- CSR build ----------------
__global__ void csr_count(const int* __restrict__ esrc) {
    int e = blockIdx.x * blockDim.x + threadIdx.x;
    if (e < NE) atomicAdd(&g_cnt[esrc[e]], 1);
}
__global__ void scan_local() {
    __shared__ int sh[256];
    int i = blockIdx.x * 256 + threadIdx.x;
    int v = (i < NND) ? g_cnt[i] : 0;
    sh[threadIdx.x] = v;
    __syncthreads();
    #pragma unroll
    for (int off = 1; off < 256; off <<= 1) {
        int t = (threadIdx.x >= off) ? sh[threadIdx.x - off] : 0;
        __syncthreads();
        sh[threadIdx.x] += t;
        __syncthreads();
    }
    if (i < NND) g_excl[i] = sh[threadIdx.x] - v;
    if (threadIdx.x == 255) g_bsum[blockIdx.x] = sh[255];
}
__global__ void scan_bsum() {
    __shared__ int sh[256];
    int v = (threadIdx.x < NB_SCAN) ? g_bsum[threadIdx.x] : 0;
    sh[threadIdx.x] = v;
    __syncthreads();
    #pragma unroll
    for (int off = 1; off < 256; off <<= 1) {
        int t = (threadIdx.x >= off) ? sh[threadIdx.x - off] : 0;
        __syncthreads();
        sh[threadIdx.x] += t;
        __syncthreads();
    }
    g_boff[threadIdx.x] = sh[threadIdx.x] - v;
}
__global__ void scan_add() {
    int i = blockIdx.x * blockDim.x + threadIdx.x;
    if (i < NND) {
        int r = g_excl[i] + g_boff[i >> 8];
        g_row[i] = r;
        g_pos[i] = r;
    }
    if (i == 0) g_row[NND] = NE;
}
__global__ void csr_fill(const int* __restrict__ esrc, const int* __restrict__ esnk,
                         const float* __restrict__ dist) {
    int e = blockIdx.x * blockDim.x + threadIdx.x;
    if (e >= NE) return;
    int p = atomicAdd(&g_pos[esrc[e]], 1);
    g_esnk_s[p] = esnk[e];
    g_edist_s[p] = dist[e];
}

// ---------------- gathers (no atomics) ----------------
// warp per node: mx[n] = sum over edges of x[snk]
__global__ void gather_x() {
    int gt = blockIdx.x * blockDim.x + threadIdx.x;
    int node = gt >> 5, lane = gt & 31;
    if (node >= NND) return;
    int s = g_row[node], e = g_row[node + 1];
    float a0 = 0.f, a1 = 0.f;
    for (int i = s; i < e; i++) {
        int snk = g_esnk_s[i] << 6;
        a0 += g_x[snk + lane];
        a1 += g_x[snk + 32 + lane];
    }
    g_mx[(node << 6) + lane] = a0;
    g_mx[(node << 6) + 32 + lane] = a1;
}

// thread per node: mrbf[n][f] = sum over edges of exp(-(d-shift_f)^2)
// identity: with t=d-0.8, val_f = exp(-t^2) * u^f * w^(f^2), u=exp(0.2t), w=exp(-0.01)
// ratio val_f/val_{f-1} = u * w^(2f-1): recurrence with r *= w^2.
__global__ void gather_rbf() {
    int node = blockIdx.x * blockDim.x + threadIdx.x;
    if (node >= NND) return;
    int s = g_row[node], e = g_row[node + 1];
    float acc[NS];
    #pragma unroll
    for (int f = 0; f < NS; f++) acc[f] = 0.f;
    for (int i = s; i < e; i++) {
        float t = g_edist_s[i] - 0.8f;
        float v = __expf(-t * t);
        float u = __expf(0.2f * t);
        float r = u * 0.99004983f;        // u * w, w = exp(-0.01)
        acc[0] += v;
        #pragma unroll
        for (int f = 1; f < NS; f++) {
            v *= r;
            acc[f] += v;
            r *= 0.98019867f;             // w^2 = exp(-0.02)
        }
    }
    #pragma unroll
    for (int f = 0; f < NS; f++) g_mrbf[node * 24 + f] = acc[f];
}

// ---------------- batchnorm stats ----------------
template <int C, int OFF, int CTOT>
__global__ void stats_reg(const float* __restrict__ X) {
    int tid = threadIdx.x;
    float s = 0.f, q = 0.f;
    int stride = gridDim.x * 256;
    for (int idx = blockIdx.x * 256 + tid; idx < NND * C; idx += stride) {
        float v = X[idx];
        s += v; q += v * v;
    }
    __shared__ float sh[512];
    sh[tid] = s; sh[256 + tid] = q;
    __syncthreads();
    if (tid < C) {
        float S = 0.f, Q = 0.f;
        #pragma unroll 4
        for (int j = tid; j < 256; j += C) { S += sh[j]; Q += sh[256 + j]; }
        atomicAdd(&g_stats[OFF + tid], S);
        atomicAdd(&g_stats[CTOT + OFF + tid], Q);
    }
}

__global__ void stats_rbf() {
    __shared__ float ss[24], sq[24];
    if (threadIdx.x < 24) { ss[threadIdx.x] = 0.f; sq[threadIdx.x] = 0.f; }
    __syncthreads();
    int stride = gridDim.x * blockDim.x;
    for (int idx = blockIdx.x * blockDim.x + threadIdx.x; idx < NND * 24; idx += stride) {
        int c = idx % 24;
        if (c < NS) {
            float v = g_mrbf[idx];
            atomicAdd(&ss[c], v);
            atomicAdd(&sq[c], v * v);
        }
    }
    __syncthreads();
    if (threadIdx.x < NS) {
        atomicAdd(&g_stats[threadIdx.x], ss[threadIdx.x]);
        atomicAdd(&g_stats[MDIM + threadIdx.x], sq[threadIdx.x]);
    }
}

template <int C>
__global__ void bn_finalize(const float* __restrict__ g, const float* __restrict__ b) {
    int c = threadIdx.x;
    if (c >= C) return;
    const float inv = 1.f / (float)NND;
    float mean = g_stats[c] * inv;
    float var = fmaxf(g_stats[C + c] * inv - mean * mean, 0.f);
    float a = g[c] * rsqrtf(var + 1e-5f);
    g_ac[c] = a;
    g_ac[C + c] = b[c] - mean * a;
}

// ---------------- double-buffered tf32 mma GEMM (unchanged from R3) ----------------
template <int KTOT, int NCH, int NN, int NW, bool RELU, bool BNIN, bool RESID,
          bool SPLITA, bool ROUND_OUT>
__global__ __launch_bounds__(256)
void gemm_mma(const float* __restrict__ A, const float* __restrict__ W,
              const float* __restrict__ bias, float* __restrict__ out, int xall_off) {
    constexpr int AW = 128 * 20;
    constexpr int BW = 16 * 68;
    __shared__ __align__(16) uint32_t sbuf[2][AW + BW];

    int tid = threadIdx.x, lane = tid & 31, wid = tid >> 5;
    int warp_m = wid & 3, warp_n = wid >> 2;
    int g = lane >> 2, tig = lane & 3;
    int bm = blockIdx.x * 128, bn = blockIdx.y * 64;
    uint32_t sbase = smem_u32(sbuf);

    float acc[2][4][4] = {};

#define STAGE(cc, bb) do { \
    int k0_ = (cc) * 16; \
    uint32_t* As_ = sbuf[bb]; \
    uint32_t aAdr_ = sbase + (uint32_t)(bb) * (AW + BW) * 4; \
    uint32_t bAdr_ = aAdr_ + AW * 4; \
    if (SPLITA) { \
        _Pragma("unroll") \
        for (int j = 0; j < 8; j++) { \
            int idx = tid + j * 256; \
            int row = idx >> 4, kk = idx & 15; \
            int gr = bm + row, gk = k0_ + kk; \
            float v = 0.f; \
            if (gr < NND && gk < KTOT) { \
                v = (gk < NS) ? g_mrbf[gr * 24 + gk] : g_mx[gr * 64 + gk - NS]; \
                v = fmaf(v, g_ac[gk], g_ac[KTOT + gk]); \
            } \
            As_[row * 20 + kk] = f2tf32(v); \
        } \
    } else if (BNIN) { \
        _Pragma("unroll") \
        for (int j = 0; j < 2; j++) { \
            int idx = tid + j * 256; \
            int row = idx >> 2, kq = idx & 3; \
            int gr = bm + row, gk = k0_ + kq * 4; \
            float4 v = {0.f, 0.f, 0.f, 0.f}; \
            if (gr < NND && gk < KTOT) v = *(const float4*)(A + (size_t)gr * KTOT + gk); \
            uint4 u; \
            u.x = f2tf32((gr < NND) ? fmaf(v.x, g_ac[gk + 0], g_ac[KTOT + gk + 0]) : 0.f); \
            u.y = f2tf32((gr < NND) ? fmaf(v.y, g_ac[gk + 1], g_ac[KTOT + gk + 1]) : 0.f); \
            u.z = f2tf32((gr < NND) ? fmaf(v.z, g_ac[gk + 2], g_ac[KTOT + gk + 2]) : 0.f); \
            u.w = f2tf32((gr < NND) ? fmaf(v.w, g_ac[gk + 3], g_ac[KTOT + gk + 3]) : 0.f); \
            *(uint4*)&As_[row * 20 + kq * 4] = u; \
        } \
    } else { \
        _Pragma("unroll") \
        for (int j = 0; j < 2; j++) { \
            int idx = tid + j * 256; \
            int row = idx >> 2, kq = idx & 3; \
            int gr = bm + row, gk = k0_ + kq * 4; \
            int vld = (gr < NND && gk + 4 <= KTOT) ? 16 : 0; \
            const float* src = vld ? (A + (size_t)gr * KTOT + gk) : A; \
            cp_async16(aAdr_ + (uint32_t)(row * 20 + kq * 4) * 4, src, vld); \
        } \
    } \
    { \
        int kk = tid >> 4, nq = tid & 15; \
        int gk = k0_ + kk, gn = bn + nq * 4; \
        int vld = (gk < KTOT && gn + 4 <= NW) ? 16 : 0; \
        const float* src = vld ? (W + (size_t)gk * NW + gn) : W; \
        cp_async16(bAdr_ + (uint32_t)(kk * 68 + nq * 4) * 4, src, vld); \
    } \
    asm volatile("cp.async.commit_group;" ::: "memory"); \
} while (0)

    STAGE(0, 0);
    for (int c = 0; c < NCH; c++) {
        if (c + 1 < NCH) {
            STAGE(c + 1, (c + 1) & 1);
            asm volatile("cp.async.wait_group 1;" ::: "memory");
        } else {
            asm volatile("cp.async.wait_group 0;" ::: "memory");
        }
        __syncthreads();
        const uint32_t* As = sbuf[c & 1];
        const uint32_t* Bs = sbuf[c & 1] + AW;
        #pragma unroll
        for (int ks = 0; ks < 2; ks++) {
            int kb = ks * 8;
            uint32_t af[2][4], bf[4][2];
            #pragma unroll
            for (int mt = 0; mt < 2; mt++) {
                int r0 = (warp_m * 32 + mt * 16 + g) * 20;
                af[mt][0] = As[r0 + kb + tig];
                af[mt][1] = As[r0 + 160 + kb + tig];
                af[mt][2] = As[r0 + kb + tig + 4];
                af[mt][3] = As[r0 + 160 + kb + tig + 4];
            }
            #pragma unroll
            for (int nt = 0; nt < 4; nt++) {
                int cc = warp_n * 32 + nt * 8 + g;
                bf[nt][0] = Bs[(kb + tig) * 68 + cc];
                bf[nt][1] = Bs[(kb + tig + 4) * 68 + cc];
            }
            #pragma unroll
            for (int mt = 0; mt < 2; mt++)
                #pragma unroll
                for (int nt = 0; nt < 4; nt++)
                    mma_tf32(acc[mt][nt], af[mt], bf[nt]);
        }
        __syncthreads();
    }
#undef STAGE

    #pragma unroll
    for (int mt = 0; mt < 2; mt++) {
        #pragma unroll
        for (int nt = 0; nt < 4; nt++) {
            int r0 = bm + warp_m * 32 + mt * 16 + g;
            int c0 = bn + warp_n * 32 + nt * 8 + tig * 2;
            float* d = acc[mt][nt];
            #pragma unroll
            for (int h = 0; h < 2; h++) {
                int r = r0 + h * 8;
                if (r < NND && c0 < NN) {
                    float v0 = d[h * 2 + 0] + __ldg(bias + c0);
                    float v1 = d[h * 2 + 1] + __ldg(bias + c0 + 1);
                    if (RELU) { v0 = fmaxf(v0, 0.f); v1 = fmaxf(v1, 0.f); }
                    if (RESID) {
                        float2 xo = *(float2*)&g_x[r * EDIM + c0];
                        float2 xn = {xo.x + 0.1f * v0, xo.y + 0.1f * v1};
                        *(float2*)&g_x[r * EDIM + c0] = xn;
                        *(float2*)&g_xall[r * RDIM + xall_off + c0] = xn;
                    } else {
                        if (ROUND_OUT) {
                            v0 = __uint_as_float(f2tf32(v0));
                            v1 = __uint_as_float(f2tf32(v1));
                        }
                        *(float2*)&out[(size_t)r * NN + c0] = {v0, v1};
                    }
                }
            }
        }
    }
}

// ---------------- final layer (H->1) + molecule scatter ----------------
__global__ void readout_final(const float* __restrict__ h, const float* __restrict__ w,
                              const float* __restrict__ b4, const int* __restrict__ mol,
                              float* __restrict__ y) {
    int gt = blockIdx.x * blockDim.x + threadIdx.x;
    int node = gt >> 5, lane = gt & 31;
    if (node >= NND) return;
    float s = 0.f;
    for (int k = lane; k < HH; k += 32) s += h[node * HH + k] * w[k];
    #pragma unroll
    for (int o = 16; o; o >>= 1) s += __shfl_xor_sync(0xffffffffu, s, o);
    if (lane == 0) atomicAdd(&y[mol[node]], s + b4[0]);
}

// ---------------- launch ----------------
extern "C" void kernel_launch(void* const* d_in, const int* in_sizes, int n_in,
                              void* d_out, int out_size) {
    const int*   z     = (const int*)d_in[0];
    const int*   eidx  = (const int*)d_in[1];
    const float* dist  = (const float*)d_in[2];
    const int*   mol   = (const int*)d_in[3];
    const float* emb   = (const float*)d_in[4];
    const float* up_bn_g = (const float*)d_in[5];
    const float* up_bn_b = (const float*)d_in[6];
    const float* up_w1 = (const float*)d_in[7];
    const float* up_b1 = (const float*)d_in[8];
    const float* up_w2 = (const float*)d_in[9];
    const float* up_b2 = (const float*)d_in[10];
    const float* up_w3 = (const float*)d_in[11];
    const float* up_b3 = (const float*)d_in[12];
    const float* up_w4 = (const float*)d_in[13];
    const float* up_b4 = (const float*)d_in[14];
    const float* ro_bn_g = (const float*)d_in[15];
    const float* ro_bn_b = (const float*)d_in[16];
    const float* ro_w1 = (const float*)d_in[17];
    const float* ro_b1 = (const float*)d_in[18];
    const float* ro_w2 = (const float*)d_in[19];
    const float* ro_b2 = (const float*)d_in[20];
    const float* ro_w3 = (const float*)d_in[21];
    const float* ro_b3 = (const float*)d_in[22];
    const float* ro_w4 = (const float*)d_in[23];
    const float* ro_b4 = (const float*)d_in[24];
    float* y = (float*)d_out;

    float *pmx, *ph1, *ph2, *pxall, *pstats, *pwT;
    int* pcnt;
    cudaGetSymbolAddress((void**)&pmx, g_mx);
    cudaGetSymbolAddress((void**)&ph1, g_h1);
    cudaGetSymbolAddress((void**)&ph2, g_h2);
    cudaGetSymbolAddress((void**)&pxall, g_xall);
    cudaGetSymbolAddress((void**)&pstats, g_stats);
    cudaGetSymbolAddress((void**)&pwT, g_wT);
    cudaGetSymbolAddress((void**)&pcnt, g_cnt);

    zero_kernel<<<(NMOLS + 255) / 256, 256>>>(y, NMOLS);
    embed_kernel<<<(NND * EDIM + 255) / 256, 256>>>(z, emb);

    // pre-round weights to tf32
    round_w<<<(52200 + 255) / 256, 256>>>(up_w1, pwT + WT_UP1, 52200);
    round_w<<<(120000 + 255) / 256, 256>>>(up_w2, pwT + WT_UP2, 120000);
    round_w<<<(120000 + 255) / 256, 256>>>(up_w3, pwT + WT_UP3, 120000);
    round_w<<<(38400 + 255) / 256, 256>>>(up_w4, pwT + WT_UP4, 38400);
    round_w<<<(51200 + 255) / 256, 256>>>(ro_w1, pwT + WT_RO1, 51200);
    round_w<<<(40000 + 255) / 256, 256>>>(ro_w2, pwT + WT_RO2, 40000);
    round_w<<<(40000 + 255) / 256, 256>>>(ro_w3, pwT + WT_RO3, 40000);

    // CSR build
    zero_int<<<(NND + 255) / 256, 256>>>(pcnt, NND);
    csr_count<<<(NE + 255) / 256, 256>>>(eidx);
    scan_local<<<NB_SCAN, 256>>>();
    scan_bsum<<<1, 256>>>();
    scan_add<<<(NND + 255) / 256, 256>>>();
    csr_fill<<<(NE + 255) / 256, 256>>>(eidx, eidx + NE, dist);

    // one-time rbf gather + its pass-invariant stats
    zero_kernel<<<2, 256>>>(pstats, 2 * RDIM);
    gather_rbf<<<(NND + 255) / 256, 256>>>();
    stats_rbf<<<296, 256>>>();

    const int GB = (NND + 127) / 128;   // 391
    dim3 gH(GB, 4), gE(GB, 1);

    for (int t = 0; t < 3; t++) {
        gather_x<<<(NND * 32 + 255) / 256, 256>>>();
        zero_kernel<<<1, 64>>>(pstats + NS, EDIM);
        zero_kernel<<<1, 64>>>(pstats + MDIM + NS, EDIM);
        stats_reg<EDIM, NS, MDIM><<<296, 256>>>(pmx);
        bn_finalize<MDIM><<<1, 256>>>(up_bn_g + t * MDIM, up_bn_b + t * MDIM);
        gemm_mma<MDIM, 6, HH, HH, true, true, false, true, true><<<gH, 256>>>(
            nullptr, pwT + WT_UP1 + t * MDIM * HH, up_b1 + t * HH, ph1, 0);
        gemm_mma<HH, 13, HH, HH, true, false, false, false, true><<<gH, 256>>>(
            ph1, pwT + WT_UP2 + t * HH * HH, up_b2 + t * HH, ph2, 0);
        gemm_mma<HH, 13, HH, HH, true, false, false, false, true><<<gH, 256>>>(
            ph2, pwT + WT_UP3 + t * HH * HH, up_b3 + t * HH, ph1, 0);
        gemm_mma<HH, 13, EDIM, EDIM, false, false, true, false, false><<<gE, 256>>>(
            ph1, pwT + WT_UP4 + t * HH * EDIM, up_b4 + t * EDIM, nullptr, EDIM * (t + 1));
    }

    zero_kernel<<<2, 256>>>(pstats, 2 * RDIM);
    stats_reg<RDIM, 0, RDIM><<<296, 256>>>(pxall);
    bn_finalize<RDIM><<<1, 256>>>(ro_bn_g, ro_bn_b);
    gemm_mma<RDIM, 16, HH, HH, true, true, false, false, true><<<gH, 256>>>(
        pxall, pwT + WT_RO1, ro_b1, ph1, 0);
    gemm_mma<HH, 13, HH, HH, true, false, false, false, true><<<gH, 256>>>(
        ph1, pwT + WT_RO2, ro_b2, ph2, 0);
    gemm_mma<HH, 13, HH, HH, true, false, false, false, true><<<gH, 256>>>(
        ph2, pwT + WT_RO3, ro_b3, ph1, 0);
    readout_final<<<(NND * 32 + 255) / 256, 256>>>(ph1, ro_w4, ro_b4, mol, y);
}

// round 9
// speedup vs baseline: 3.3163x; 1.3444x over previous
#include <cuda_runtime.h>
#include <cuda_fp16.h>
#include <cstdint>

#define NND 50000
#define NE  800000
#define EDIM 64
#define NS  23
#define MDIM 87
#define HH  200
#define RDIM 256
#define NMOLS 2048
#define NB_SCAN 196   // ceil(NND/256)

// ---------------- scratch (device globals; no allocations) ----------------
__device__ float  g_x[NND * EDIM];
__device__ float  g_xall[NND * RDIM];
__device__ float  g_mrbf[NND * 24];
__device__ float  g_mx[NND * EDIM];
__device__ __half g_h1[NND * HH];
__device__ __half g_h2[NND * HH];
__device__ float  g_stats[2 * RDIM];
__device__ float  g_ac[2 * RDIM];
__device__ __half g_wH[482000];         // n-major [NW][KPAD] fp16 weights
// CSR scratch
__device__ int   g_cnt[NND];
__device__ int   g_excl[NND];
__device__ int   g_bsum[256];
__device__ int   g_boff[256];
__device__ int   g_row[NND + 1];
__device__ int   g_pos[NND];
__device__ int   g_esnk_s[NE];
__device__ float g_edist_s[NE];

// wH offsets (halves)
#define WH_UP1 0        // 3 x 200x96
#define WH_UP2 57600    // 3 x 200x208
#define WH_UP3 182400   // 3 x 200x208
#define WH_UP4 307200   // 3 x 64x208
#define WH_RO1 347136   // 200x256
#define WH_RO2 398336   // 200x208
#define WH_RO3 439936   // 200x208

// ---------------- helpers ----------------
__device__ __forceinline__ uint32_t smem_u32(const void* p) {
    uint32_t a;
    asm("{ .reg .u64 t; cvta.to.shared.u64 t, %1; cvt.u32.u64 %0, t; }" : "=r"(a) : "l"(p));
    return a;
}
__device__ __forceinline__ void cp_async16(uint32_t dst, const void* src, int valid) {
    asm volatile("cp.async.cg.shared.global [%0], [%1], 16, %2;"
                 :: "r"(dst), "l"(src), "r"(valid) : "memory");
}
__device__ __forceinline__ void mma_f16(float* d, const uint32_t* a, const uint32_t* b) {
    asm volatile(
        "mma.sync.aligned.m16n8k16.row.col.f32.f16.f16.f32 "
        "{%0,%1,%2,%3}, {%4,%5,%6,%7}, {%8,%9}, {%0,%1,%2,%3};"
        : "+f"(d[0]), "+f"(d[1]), "+f"(d[2]), "+f"(d[3])
        : "r"(a[0]), "r"(a[1]), "r"(a[2]), "r"(a[3]), "r"(b[0]), "r"(b[1]));
}
__device__ __forceinline__ uint32_t pack_h2(float a, float b) {
    __half2 h = __floats2half2_rn(a, b);
    return *(uint32_t*)&h;
}

// ---------------- utility kernels ----------------
__global__ void zero_kernel(float* __restrict__ p, int n) {
    int i = blockIdx.x * blockDim.x + threadIdx.x;
    if (i < n) p[i] = 0.f;
}
__global__ void zero_int(int* __restrict__ p, int n) {
    int i = blockIdx.x * blockDim.x + threadIdx.x;
    if (i < n) p[i] = 0;
}
__global__ void embed_kernel(const int* __restrict__ z, const float* __restrict__ emb) {
    int i = blockIdx.x * blockDim.x + threadIdx.x;
    if (i >= NND * EDIM) return;
    int n = i >> 6, d = i & 63;
    float v = emb[(z[n] << 6) + d];
    g_x[i] = v;
    g_xall[(n << 8) + d] = v;
}
// in [nt][K][NW] float -> out [nt][NW][KPAD] half, zero-padded
__global__ void transpose_wh(const float* __restrict__ in, __half* __restrict__ out,
                             int K, int NW, int KPAD, int nt) {
    int per = NW * KPAD, total = per * nt;
    for (int i = blockIdx.x * blockDim.x + threadIdx.x; i < total; i += gridDim.x * blockDim.x) {
        int t = i / per, rem = i - t * per;
        int n = rem / KPAD, k = rem - n * KPAD;
        float v = (k < K) ? in[(size_t)t * K * NW + (size_t)k * NW + n] : 0.f;
        out[i] = __float2half(v);
    }
}

// ---------------- CSR build ----------------
__global__ void csr_count(const int* __restrict__ esrc) {
    int e = blockIdx.x * blockDim.x + threadIdx.x;
    if (e < NE) atomicAdd(&g_cnt[esrc[e]], 1);
}
__global__ void scan_local() {
    __shared__ int sh[256];
    int i = blockIdx.x * 256 + threadIdx.x;
    int v = (i < NND) ? g_cnt[i] : 0;
    sh[threadIdx.x] = v;
    __syncthreads();
    #pragma unroll
    for (int off = 1; off < 256; off <<= 1) {
        int t = (threadIdx.x >= off) ? sh[threadIdx.x - off] : 0;
        __syncthreads();
        sh[threadIdx.x] += t;
        __syncthreads();
    }
    if (i < NND) g_excl[i] = sh[threadIdx.x] - v;
    if (threadIdx.x == 255) g_bsum[blockIdx.x] = sh[255];
}
__global__ void scan_bsum() {
    __shared__ int sh[256];
    int v = (threadIdx.x < NB_SCAN) ? g_bsum[threadIdx.x] : 0;
    sh[threadIdx.x] = v;
    __syncthreads();
    #pragma unroll
    for (int off = 1; off < 256; off <<= 1) {
        int t = (threadIdx.x >= off) ? sh[threadIdx.x - off] : 0;
        __syncthreads();
        sh[threadIdx.x] += t;
        __syncthreads();
    }
    g_boff[threadIdx.x] = sh[threadIdx.x] - v;
}
__global__ void scan_add() {
    int i = blockIdx.x * blockDim.x + threadIdx.x;
    if (i < NND) {
        int r = g_excl[i] + g_boff[i >> 8];
        g_row[i] = r;
        g_pos[i] = r;
    }
    if (i == 0) g_row[NND] = NE;
}
__global__ void csr_fill(const int* __restrict__ esrc, const int* __restrict__ esnk,
                         const float* __restrict__ dist) {
    int e = blockIdx.x * blockDim.x + threadIdx.x;
    if (e >= NE) return;
    int p = atomicAdd(&g_pos[esrc[e]], 1);
    g_esnk_s[p] = esnk[e];
    g_edist_s[p] = dist[e];
}

// ---------------- gathers ----------------
__global__ void gather_x() {
    int gt = blockIdx.x * blockDim.x + threadIdx.x;
    int node = gt >> 5, lane = gt & 31;
    if (node >= NND) return;
    int s = g_row[node], e = g_row[node + 1];
    float a0 = 0.f, a1 = 0.f;
    for (int i = s; i < e; i++) {
        int snk = g_esnk_s[i] << 6;
        a0 += g_x[snk + lane];
        a1 += g_x[snk + 32 + lane];
    }
    g_mx[(node << 6) + lane] = a0;
    g_mx[(node << 6) + 32 + lane] = a1;
}
__global__ void gather_rbf() {
    int node = blockIdx.x * blockDim.x + threadIdx.x;
    if (node >= NND) return;
    int s = g_row[node], e = g_row[node + 1];
    float acc[NS];
    #pragma unroll
    for (int f = 0; f < NS; f++) acc[f] = 0.f;
    for (int i = s; i < e; i++) {
        float t = g_edist_s[i] - 0.8f;
        float v = __expf(-t * t);
        float u = __expf(0.2f * t);
        float r = u * 0.99004983f;
        acc[0] += v;
        #pragma unroll
        for (int f = 1; f < NS; f++) {
            v *= r;
            acc[f] += v;
            r *= 0.98019867f;
        }
    }
    #pragma unroll
    for (int f = 0; f < NS; f++) g_mrbf[node * 24 + f] = acc[f];
}

// ---------------- batchnorm stats ----------------
template <int C, int OFF, int CTOT>
__global__ void stats_reg(const float* __restrict__ X) {
    int tid = threadIdx.x;
    float s = 0.f, q = 0.f;
    int stride = gridDim.x * 256;
    for (int idx = blockIdx.x * 256 + tid; idx < NND * C; idx += stride) {
        float v = X[idx];
        s += v; q += v * v;
    }
    __shared__ float sh[512];
    sh[tid] = s; sh[256 + tid] = q;
    __syncthreads();
    if (tid < C) {
        float S = 0.f, Q = 0.f;
        #pragma unroll 4
        for (int j = tid; j < 256; j += C) { S += sh[j]; Q += sh[256 + j]; }
        atomicAdd(&g_stats[OFF + tid], S);
        atomicAdd(&g_stats[CTOT + OFF + tid], Q);
    }
}
__global__ void stats_rbf() {
    __shared__ float ss[24], sq[24];
    if (threadIdx.x < 24) { ss[threadIdx.x] = 0.f; sq[threadIdx.x] = 0.f; }
    __syncthreads();
    int stride = gridDim.x * blockDim.x;
    for (int idx = blockIdx.x * blockDim.x + threadIdx.x; idx < NND * 24; idx += stride) {
        int c = idx % 24;
        if (c < NS) {
            float v = g_mrbf[idx];
            atomicAdd(&ss[c], v);
            atomicAdd(&sq[c], v * v);
        }
    }
    __syncthreads();
    if (threadIdx.x < NS) {
        atomicAdd(&g_stats[threadIdx.x], ss[threadIdx.x]);
        atomicAdd(&g_stats[MDIM + threadIdx.x], sq[threadIdx.x]);
    }
}
template <int C>
__global__ void bn_finalize(const float* __restrict__ g, const float* __restrict__ b) {
    int c = threadIdx.x;
    if (c >= C) return;
    const float inv = 1.f / (float)NND;
    float mean = g_stats[c] * inv;
    float var = fmaxf(g_stats[C + c] * inv - mean * mean, 0.f);
    float a = g[c] * rsqrtf(var + 1e-5f);
    g_ac[c] = a;
    g_ac[C + c] = b[c] - mean * a;
}

// ---------------- fp16 m16n8k16 double-buffered GEMM ----------------
// D[128 x NN] = epi(A' @ WH^T + bias). WH: [NW][KPAD] n-major half.
// Paths: SPLITA (mrbf+mx, BN fold), BNIN (fp32 A, BN fold), else cp.async half A.
// RESID: g_x += 0.1*D (fp32) + g_xall slice; else store half to out.
template <int KTOT, int NCH, int NN, int NW, bool RELU, bool BNIN, bool RESID, bool SPLITA>
__global__ __launch_bounds__(256)
void gemm_f16(const void* __restrict__ Ain, const __half* __restrict__ WH,
              const float* __restrict__ bias, __half* __restrict__ out, int xall_off) {
    constexpr int KPAD = NCH * 16;
    constexpr int AW = 128 * 12;   // A words per stage ([row][8 half2 words], stride 12)
    constexpr int BW = 64 * 12;    // B words per stage
    __shared__ __align__(16) uint32_t sbuf[2][AW + BW];

    int tid = threadIdx.x, lane = tid & 31, wid = tid >> 5;
    int warp_m = wid & 3, warp_n = wid >> 2;
    int g = lane >> 2, tig = lane & 3;
    int bm = blockIdx.x * 128, bn = blockIdx.y * 64;
    uint32_t sbase = smem_u32(sbuf);

    float acc[2][4][4] = {};

#define STAGE(cc, bb) do { \
    int k0_ = (cc) * 16; \
    uint32_t* As_ = sbuf[bb]; \
    uint32_t aAdr_ = sbase + (uint32_t)(bb) * (AW + BW) * 4; \
    uint32_t bAdr_ = aAdr_ + AW * 4; \
    if (SPLITA) { \
        _Pragma("unroll") \
        for (int j = 0; j < 4; j++) { \
            int idx = tid + j * 256; \
            int row = idx >> 3, w = idx & 7; \
            int gr = bm + row, gk = k0_ + 2 * w; \
            float v0 = 0.f, v1 = 0.f; \
            if (gr < NND) { \
                if (gk < KTOT) { \
                    v0 = (gk < NS) ? g_mrbf[gr * 24 + gk] : g_mx[gr * 64 + gk - NS]; \
                    v0 = fmaf(v0, g_ac[gk], g_ac[KTOT + gk]); \
                } \
                if (gk + 1 < KTOT) { \
                    v1 = (gk + 1 < NS) ? g_mrbf[gr * 24 + gk + 1] : g_mx[gr * 64 + gk + 1 - NS]; \
                    v1 = fmaf(v1, g_ac[gk + 1], g_ac[KTOT + gk + 1]); \
                } \
            } \
            As_[row * 12 + w] = pack_h2(v0, v1); \
        } \
    } else if (BNIN) { \
        const float* Af = (const float*)Ain; \
        _Pragma("unroll") \
        for (int j = 0; j < 2; j++) { \
            int idx = tid + j * 256; \
            int row = idx >> 2, wq = idx & 3; \
            int gr = bm + row, gk = k0_ + wq * 4; \
            float4 v = {0.f, 0.f, 0.f, 0.f}; \
            if (gr < NND && gk + 4 <= KTOT) v = *(const float4*)(Af + (size_t)gr * KTOT + gk); \
            float f0 = (gr < NND) ? fmaf(v.x, g_ac[gk + 0], g_ac[KTOT + gk + 0]) : 0.f; \
            float f1 = (gr < NND) ? fmaf(v.y, g_ac[gk + 1], g_ac[KTOT + gk + 1]) : 0.f; \
            float f2 = (gr < NND) ? fmaf(v.z, g_ac[gk + 2], g_ac[KTOT + gk + 2]) : 0.f; \
            float f3 = (gr < NND) ? fmaf(v.w, g_ac[gk + 3], g_ac[KTOT + gk + 3]) : 0.f; \
            As_[row * 12 + wq * 2 + 0] = pack_h2(f0, f1); \
            As_[row * 12 + wq * 2 + 1] = pack_h2(f2, f3); \
        } \
    } else { \
        const __half* Ah = (const __half*)Ain; \
        int row = tid >> 1, kq = tid & 1; \
        int gr = bm + row, gk = k0_ + kq * 8; \
        int vld = (gr < NND && gk + 8 <= KTOT) ? 16 : 0; \
        const __half* src = vld ? (Ah + (size_t)gr * KTOT + gk) : Ah; \
        cp_async16(aAdr_ + (uint32_t)(row * 12 + kq * 4) * 4, src, vld); \
    } \
    if (tid < 128) { \
        int row = tid >> 1, kq = tid & 1; \
        int gn = bn + row; \
        int vld = (gn < NW) ? 16 : 0; \
        const __half* src = vld ? (WH + (size_t)gn * KPAD + k0_ + kq * 8) : WH; \
        cp_async16(bAdr_ + (uint32_t)(row * 12 + kq * 4) * 4, src, vld); \
    } \
    asm volatile("cp.async.commit_group;" ::: "memory"); \
} while (0)

    STAGE(0, 0);
    for (int c = 0; c < NCH; c++) {
        if (c + 1 < NCH) {
            STAGE(c + 1, (c + 1) & 1);
            asm volatile("cp.async.wait_group 1;" ::: "memory");
        } else {
            asm volatile("cp.async.wait_group 0;" ::: "memory");
        }
        __syncthreads();
        const uint32_t* As = sbuf[c & 1];
        const uint32_t* Bs = sbuf[c & 1] + AW;
        uint32_t af[2][4], bf[4][2];
        #pragma unroll
        for (int mt = 0; mt < 2; mt++) {
            int r0 = (warp_m * 32 + mt * 16 + g) * 12;
            af[mt][0] = As[r0 + tig];
            af[mt][1] = As[r0 + 96 + tig];
            af[mt][2] = As[r0 + tig + 4];
            af[mt][3] = As[r0 + 96 + tig + 4];
        }
        #pragma unroll
        for (int nt = 0; nt < 4; nt++) {
            int cc = (warp_n * 32 + nt * 8 + g) * 12;
            bf[nt][0] = Bs[cc + tig];
            bf[nt][1] = Bs[cc + tig + 4];
        }
        #pragma unroll
        for (int mt = 0; mt < 2; mt++)
            #pragma unroll
            for (int nt = 0; nt < 4; nt++)
                mma_f16(acc[mt][nt], af[mt], bf[nt]);
        __syncthreads();
    }
#undef STAGE

    // ---- epilogue ----
    #pragma unroll
    for (int mt = 0; mt < 2; mt++) {
        #pragma unroll
        for (int nt = 0; nt < 4; nt++) {
            int r0 = bm + warp_m * 32 + mt * 16 + g;
            int c0 = bn + warp_n * 32 + nt * 8 + tig * 2;
            float* d = acc[mt][nt];
            #pragma unroll
            for (int h = 0; h < 2; h++) {
                int r = r0 + h * 8;
                if (r < NND && c0 < NN) {
                    float v0 = d[h * 2 + 0] + __ldg(bias + c0);
                    float v1 = d[h * 2 + 1] + __ldg(bias + c0 + 1);
                    if (RELU) { v0 = fmaxf(v0, 0.f); v1 = fmaxf(v1, 0.f); }
                    if (RESID) {
                        float2 xo = *(float2*)&g_x[r * EDIM + c0];
                        float2 xn = {xo.x + 0.1f * v0, xo.y + 0.1f * v1};
                        *(float2*)&g_x[r * EDIM + c0] = xn;
                        *(float2*)&g_xall[r * RDIM + xall_off + c0] = xn;
                    } else {
                        __half2 hv = __floats2half2_rn(v0, v1);
                        *(__half2*)&out[(size_t)r * NN + c0] = hv;
                    }
                }
            }
        }
    }
}

// ---------------- final layer (H->1) + molecule scatter ----------------
__global__ void readout_final(const __half* __restrict__ h, const float* __restrict__ w,
                              const float* __restrict__ b4, const int* __restrict__ mol,
                              float* __restrict__ y) {
    int gt = blockIdx.x * blockDim.x + threadIdx.x;
    int node = gt >> 5, lane = gt & 31;
    if (node >= NND) return;
    float s = 0.f;
    for (int k = lane; k < HH; k += 32) s += __half2float(h[node * HH + k]) * w[k];
    #pragma unroll
    for (int o = 16; o; o >>= 1) s += __shfl_xor_sync(0xffffffffu, s, o);
    if (lane == 0) atomicAdd(&y[mol[node]], s + b4[0]);
}

// ---------------- launch ----------------
extern "C" void kernel_launch(void* const* d_in, const int* in_sizes, int n_in,
                              void* d_out, int out_size) {
    const int*   z     = (const int*)d_in[0];
    const int*   eidx  = (const int*)d_in[1];
    const float* dist  = (const float*)d_in[2];
    const int*   mol   = (const int*)d_in[3];
    const float* emb   = (const float*)d_in[4];
    const float* up_bn_g = (const float*)d_in[5];
    const float* up_bn_b = (const float*)d_in[6];
    const float* up_w1 = (const float*)d_in[7];
    const float* up_b1 = (const float*)d_in[8];
    const float* up_w2 = (const float*)d_in[9];
    const float* up_b2 = (const float*)d_in[10];
    const float* up_w3 = (const float*)d_in[11];
    const float* up_b3 = (const float*)d_in[12];
    const float* up_w4 = (const float*)d_in[13];
    const float* up_b4 = (const float*)d_in[14];
    const float* ro_bn_g = (const float*)d_in[15];
    const float* ro_bn_b = (const float*)d_in[16];
    const float* ro_w1 = (const float*)d_in[17];
    const float* ro_b1 = (const float*)d_in[18];
    const float* ro_w2 = (const float*)d_in[19];
    const float* ro_b2 = (const float*)d_in[20];
    const float* ro_w3 = (const float*)d_in[21];
    const float* ro_b3 = (const float*)d_in[22];
    const float* ro_w4 = (const float*)d_in[23];
    const float* ro_b4 = (const float*)d_in[24];
    float* y = (float*)d_out;

    float *pmx, *pxall, *pstats;
    __half *ph1, *ph2, *pwH;
    int* pcnt;
    cudaGetSymbolAddress((void**)&pmx, g_mx);
    cudaGetSymbolAddress((void**)&ph1, g_h1);
    cudaGetSymbolAddress((void**)&ph2, g_h2);
    cudaGetSymbolAddress((void**)&pxall, g_xall);
    cudaGetSymbolAddress((void**)&pstats, g_stats);
    cudaGetSymbolAddress((void**)&pwH, g_wH);
    cudaGetSymbolAddress((void**)&pcnt, g_cnt);

    zero_kernel<<<(NMOLS + 255) / 256, 256>>>(y, NMOLS);
    embed_kernel<<<(NND * EDIM + 255) / 256, 256>>>(z, emb);

    // weight transposes -> n-major fp16
    transpose_wh<<<256, 256>>>(up_w1, pwH + WH_UP1, MDIM, HH, 96, 3);
    transpose_wh<<<512, 256>>>(up_w2, pwH + WH_UP2, HH, HH, 208, 3);
    transpose_wh<<<512, 256>>>(up_w3, pwH + WH_UP3, HH, HH, 208, 3);
    transpose_wh<<<256, 256>>>(up_w4, pwH + WH_UP4, HH, EDIM, 208, 3);
    transpose_wh<<<256, 256>>>(ro_w1, pwH + WH_RO1, RDIM, HH, 256, 1);
    transpose_wh<<<256, 256>>>(ro_w2, pwH + WH_RO2, HH, HH, 208, 1);
    transpose_wh<<<256, 256>>>(ro_w3, pwH + WH_RO3, HH, HH, 208, 1);

    // CSR build
    zero_int<<<(NND + 255) / 256, 256>>>(pcnt, NND);
    csr_count<<<(NE + 255) / 256, 256>>>(eidx);
    scan_local<<<NB_SCAN, 256>>>();
    scan_bsum<<<1, 256>>>();
    scan_add<<<(NND + 255) / 256, 256>>>();
    csr_fill<<<(NE + 255) / 256, 256>>>(eidx, eidx + NE, dist);

    // one-time rbf gather + pass-invariant stats
    zero_kernel<<<2, 256>>>(pstats, 2 * RDIM);
    gather_rbf<<<(NND + 255) / 256, 256>>>();
    stats_rbf<<<296, 256>>>();

    const int GB = (NND + 127) / 128;   // 391
    dim3 gH(GB, 4), gE(GB, 1);

    for (int t = 0; t < 3; t++) {
        gather_x<<<(NND * 32 + 255) / 256, 256>>>();
        zero_kernel<<<1, 64>>>(pstats + NS, EDIM);
        zero_kernel<<<1, 64>>>(pstats + MDIM + NS, EDIM);
        stats_reg<EDIM, NS, MDIM><<<296, 256>>>(pmx);
        bn_finalize<MDIM><<<1, 256>>>(up_bn_g + t * MDIM, up_bn_b + t * MDIM);
        gemm_f16<MDIM, 6, HH, HH, true, false, false, true><<<gH, 256>>>(
            nullptr, pwH + WH_UP1 + t * HH * 96, up_b1 + t * HH, ph1, 0);
        gemm_f16<HH, 13, HH, HH, true, false, false, false><<<gH, 256>>>(
            ph1, pwH + WH_UP2 + t * HH * 208, up_b2 + t * HH, ph2, 0);
        gemm_f16<HH, 13, HH, HH, true, false, false, false><<<gH, 256>>>(
            ph2, pwH + WH_UP3 + t * HH * 208, up_b3 + t * HH, ph1, 0);
        gemm_f16<HH, 13, EDIM, EDIM, false, false, true, false><<<gE, 256>>>(
            ph1, pwH + WH_UP4 + t * EDIM * 208, up_b4 + t * EDIM, nullptr, EDIM * (t + 1));
    }

    zero_kernel<<<2, 256>>>(pstats, 2 * RDIM);
    stats_reg<RDIM, 0, RDIM><<<296, 256>>>(pxall);
    bn_finalize<RDIM><<<1, 256>>>(ro_bn_g, ro_bn_b);
    gemm_f16<RDIM, 16, HH, HH, true, true, false, false><<<gH, 256>>>(
        pxall, pwH + WH_RO1, ro_b1, ph1, 0);
    gemm_f16<HH, 13, HH, HH, true, false, false, false><<<gH, 256>>>(
        ph1, pwH + WH_RO2, ro_b2, ph2, 0);
    gemm_f16<HH, 13, HH, HH, true, false, false, false><<<gH, 256>>>(
        ph2, pwH + WH_RO3, ro_b3, ph1, 0);
    readout_final<<<(NND * 32 + 255) / 256, 256>>>(ph1, ro_w4, ro_b4, mol, y);
}